// round 5
// baseline (speedup 1.0000x reference)
#include <cuda_runtime.h>

// Problem constants
#define NCHIP   8
#define SEQ     2048
#define TOPK    8
#define HID     1024
#define NEXP    64
#define MAXTOK  2560
#define NPC     (SEQ * TOPK)          // 16384 assignments per chip
#define NTOT    (NCHIP * NPC)         // 131072 assignments total
#define NROWS   (NEXP * MAXTOK)       // 163840 output rows
#define METAL   8

// Output layout (flattened concat, float32):
//   [0, NROWS*HID)                       dispatched
//   [NROWS*HID, NROWS*HID + NROWS*8)     metadata
//   [... , +64)                          tokens_per_expert (value-cast to float)
#define DISP_ELEMS   ((size_t)NROWS * HID)          // 167772160
#define META_OFF     DISP_ELEMS
#define META_ELEMS   ((size_t)NROWS * METAL)        // 1310720
#define TPE_OFF      (META_OFF + META_ELEMS)        // 169082880

// Scratch (static device globals; no allocation allowed)
__device__ int g_counts[NCHIP * NEXP];
__device__ int g_off[NCHIP * NEXP];
__device__ int g_rank[NTOT];
__device__ int g_src[NROWS];

// ---------------------------------------------------------------------------
// Kernel A: per-chip scan-order ranks + per-(chip,expert) counts.
// grid = 8 (one block per chip), block = 128. Each thread owns 128 consecutive
// assignments; ranks within each chunk are assigned sequentially by the owning
// thread, chunk bases come from a per-expert exclusive scan over chunks.
// Fully deterministic (matches jnp stable-argsort rank semantics).
// ---------------------------------------------------------------------------
__global__ void k_rank(const int* __restrict__ idx) {
    __shared__ int cnt[128 * NEXP];   // 32 KB
    const int c = blockIdx.x;
    const int t = threadIdx.x;
    const int* ci = idx + c * NPC;
    int* my = cnt + t * NEXP;

    #pragma unroll
    for (int e = 0; e < NEXP; e++) my[e] = 0;

    const int n0 = t * 128;
    #pragma unroll 4
    for (int i = 0; i < 128; i++) my[ci[n0 + i]]++;
    __syncthreads();

    if (t < NEXP) {
        int run = 0;
        for (int b = 0; b < 128; b++) {
            int v = cnt[b * NEXP + t];
            cnt[b * NEXP + t] = run;
            run += v;
        }
        g_counts[c * NEXP + t] = run;
    }
    __syncthreads();

    #pragma unroll 4
    for (int i = 0; i < 128; i++) {
        int e = ci[n0 + i];
        g_rank[c * NPC + n0 + i] = my[e]++;
    }
}

// ---------------------------------------------------------------------------
// Kernel B: exclusive prefix over chips -> chip offsets; totals ->
// tokens_per_expert (value-converted to float in the output tail).
// 1 block, 64 threads.
// ---------------------------------------------------------------------------
__global__ void k_scan(float* __restrict__ out) {
    const int e = threadIdx.x;   // 0..63, flat (chip*8 + local) order
    int run = 0;
    for (int c = 0; c < NCHIP; c++) {
        g_off[c * NEXP + e] = run;
        run += g_counts[c * NEXP + e];
    }
    out[TPE_OFF + e] = (float)run;
}

// ---------------------------------------------------------------------------
// Kernel C0: init the row->assignment table to -1 (empty).
// ---------------------------------------------------------------------------
__global__ void k_init_src() {
    int r = blockIdx.x * blockDim.x + threadIdx.x;
    if (r < NROWS) g_src[r] = -1;
}

// ---------------------------------------------------------------------------
// Kernel C: scatter assignment ids into the row table. dest slots are unique
// by construction, so plain stores. Drop only if dest falls off the whole
// (E*MAXTOK) buffer — exact numpy mode="drop" semantics (spill into next
// expert region would be kept, but cannot occur at these sizes).
// ---------------------------------------------------------------------------
__global__ void k_scatter(const int* __restrict__ idx) {
    int a = blockIdx.x * blockDim.x + threadIdx.x;
    if (a >= NTOT) return;
    int c = a >> 14;               // a / NPC
    int e = idx[a];
    int dest = e * MAXTOK + g_off[c * NEXP + e] + g_rank[a];
    if (dest < NROWS) g_src[dest] = a;
}

// ---------------------------------------------------------------------------
// Kernel D: the big gather. One block per output row; 256 threads copy the
// 4KB token row as float4 (or zero-fill), threads 0/1 write the metadata row.
// Writes are perfectly sequential over the output; x reads are gathered but
// x (64MB) fits in L2.
// ---------------------------------------------------------------------------
__global__ void __launch_bounds__(256) k_gather(const float* __restrict__ x,
                                                const float* __restrict__ w,
                                                float* __restrict__ out) {
    const int r = blockIdx.x;
    const int t = threadIdx.x;
    const int a = g_src[r];

    float4* drow = reinterpret_cast<float4*>(out + (size_t)r * HID);
    float4* mrow = reinterpret_cast<float4*>(out + META_OFF + (size_t)r * METAL);

    if (a < 0) {
        drow[t] = make_float4(0.f, 0.f, 0.f, 0.f);
        if (t < 2) mrow[t] = make_float4(-1.f, -1.f, -1.f, -1.f);
    } else {
        const int c = a >> 14;
        const int n = a & (NPC - 1);
        const int s = n >> 3;
        const int k = n & 7;
        const float4* xr = reinterpret_cast<const float4*>(
            x + ((size_t)c * SEQ + s) * HID);
        drow[t] = __ldg(&xr[t]);
        if (t == 0) {
            mrow[0] = make_float4((float)c, (float)s, (float)k,
                                  (float)(r / MAXTOK));
        } else if (t == 1) {
            float wt = __ldg(&w[(c * SEQ + s) * TOPK + k]);
            mrow[1] = make_float4(wt, 0.f, 0.f, 0.f);
        }
    }
}

// ---------------------------------------------------------------------------
extern "C" void kernel_launch(void* const* d_in, const int* in_sizes, int n_in,
                              void* d_out, int out_size) {
    const float* x   = (const float*)d_in[0];   // (8,2048,1024) f32
    const float* wts = (const float*)d_in[1];   // (8,2048,8) f32
    const int*   idx = (const int*)d_in[2];     // (8,2048,8) i32
    float* out = (float*)d_out;

    k_rank<<<NCHIP, 128>>>(idx);
    k_scan<<<1, NEXP>>>(out);
    k_init_src<<<(NROWS + 255) / 256, 256>>>();
    k_scatter<<<(NTOT + 255) / 256, 256>>>(idx);
    k_gather<<<NROWS, 256>>>(x, wts, out);
}

// round 6
// speedup vs baseline: 1.0013x; 1.0013x over previous
#include <cuda_runtime.h>

// Problem constants
#define NCHIP   8
#define SEQ     2048
#define TOPK    8
#define HID     1024
#define NEXP    64
#define MAXTOK  2560
#define NPC     (SEQ * TOPK)          // 16384 assignments per chip
#define NTOT    (NCHIP * NPC)         // 131072 assignments total
#define NROWS   (NEXP * MAXTOK)       // 163840 output rows
#define METAL   8

// Output layout (flattened concat, float32):
//   [0, NROWS*HID)                       dispatched
//   [NROWS*HID, NROWS*HID + NROWS*8)     metadata
//   [... , +64)                          tokens_per_expert (value-cast to float)
#define DISP_ELEMS   ((size_t)NROWS * HID)          // 167772160
#define META_OFF     DISP_ELEMS
#define META_ELEMS   ((size_t)NROWS * METAL)        // 1310720
#define TPE_OFF      (META_OFF + META_ELEMS)        // 169082880

// Scratch (static device globals; no allocation allowed)
__device__ int g_counts[NCHIP * NEXP];
__device__ int g_off[NCHIP * NEXP];
__device__ int g_rank[NTOT];
__device__ int g_src[NROWS];

// ---------------------------------------------------------------------------
// Kernel A: per-chip scan-order ranks + per-(chip,expert) counts.
// grid = 8 (one block per chip), block = 128. Each thread owns 128 consecutive
// assignments; ranks within each chunk are assigned sequentially by the owning
// thread, chunk bases come from a per-expert exclusive scan over chunks.
// Fully deterministic (matches jnp stable-argsort rank semantics).
// ---------------------------------------------------------------------------
__global__ void k_rank(const int* __restrict__ idx) {
    __shared__ int cnt[128 * NEXP];   // 32 KB
    const int c = blockIdx.x;
    const int t = threadIdx.x;
    const int* ci = idx + c * NPC;
    int* my = cnt + t * NEXP;

    #pragma unroll
    for (int e = 0; e < NEXP; e++) my[e] = 0;

    const int n0 = t * 128;
    #pragma unroll 4
    for (int i = 0; i < 128; i++) my[ci[n0 + i]]++;
    __syncthreads();

    if (t < NEXP) {
        int run = 0;
        for (int b = 0; b < 128; b++) {
            int v = cnt[b * NEXP + t];
            cnt[b * NEXP + t] = run;
            run += v;
        }
        g_counts[c * NEXP + t] = run;
    }
    __syncthreads();

    #pragma unroll 4
    for (int i = 0; i < 128; i++) {
        int e = ci[n0 + i];
        g_rank[c * NPC + n0 + i] = my[e]++;
    }
}

// ---------------------------------------------------------------------------
// Kernel B: exclusive prefix over chips -> chip offsets; totals ->
// tokens_per_expert (value-converted to float in the output tail).
// 1 block, 64 threads.
// ---------------------------------------------------------------------------
__global__ void k_scan(float* __restrict__ out) {
    const int e = threadIdx.x;   // 0..63, flat (chip*8 + local) order
    int run = 0;
    for (int c = 0; c < NCHIP; c++) {
        g_off[c * NEXP + e] = run;
        run += g_counts[c * NEXP + e];
    }
    out[TPE_OFF + e] = (float)run;
}

// ---------------------------------------------------------------------------
// Kernel C0: init the row->assignment table to -1 (empty).
// ---------------------------------------------------------------------------
__global__ void k_init_src() {
    int r = blockIdx.x * blockDim.x + threadIdx.x;
    if (r < NROWS) g_src[r] = -1;
}

// ---------------------------------------------------------------------------
// Kernel C: scatter assignment ids into the row table. dest slots are unique
// by construction, so plain stores. Drop only if dest falls off the whole
// (E*MAXTOK) buffer — exact numpy mode="drop" semantics (spill into next
// expert region would be kept, but cannot occur at these sizes).
// ---------------------------------------------------------------------------
__global__ void k_scatter(const int* __restrict__ idx) {
    int a = blockIdx.x * blockDim.x + threadIdx.x;
    if (a >= NTOT) return;
    int c = a >> 14;               // a / NPC
    int e = idx[a];
    int dest = e * MAXTOK + g_off[c * NEXP + e] + g_rank[a];
    if (dest < NROWS) g_src[dest] = a;
}

// ---------------------------------------------------------------------------
// Kernel D: the big gather. One block per output row; 256 threads copy the
// 4KB token row as float4 (or zero-fill), threads 0/1 write the metadata row.
// Writes are perfectly sequential over the output; x reads are gathered but
// x (64MB) fits in L2.
// ---------------------------------------------------------------------------
__global__ void __launch_bounds__(256) k_gather(const float* __restrict__ x,
                                                const float* __restrict__ w,
                                                float* __restrict__ out) {
    const int r = blockIdx.x;
    const int t = threadIdx.x;
    const int a = g_src[r];

    float4* drow = reinterpret_cast<float4*>(out + (size_t)r * HID);
    float4* mrow = reinterpret_cast<float4*>(out + META_OFF + (size_t)r * METAL);

    if (a < 0) {
        drow[t] = make_float4(0.f, 0.f, 0.f, 0.f);
        if (t < 2) mrow[t] = make_float4(-1.f, -1.f, -1.f, -1.f);
    } else {
        const int c = a >> 14;
        const int n = a & (NPC - 1);
        const int s = n >> 3;
        const int k = n & 7;
        const float4* xr = reinterpret_cast<const float4*>(
            x + ((size_t)c * SEQ + s) * HID);
        drow[t] = __ldg(&xr[t]);
        if (t == 0) {
            mrow[0] = make_float4((float)c, (float)s, (float)k,
                                  (float)(r / MAXTOK));
        } else if (t == 1) {
            float wt = __ldg(&w[(c * SEQ + s) * TOPK + k]);
            mrow[1] = make_float4(wt, 0.f, 0.f, 0.f);
        }
    }
}

// ---------------------------------------------------------------------------
extern "C" void kernel_launch(void* const* d_in, const int* in_sizes, int n_in,
                              void* d_out, int out_size) {
    const float* x   = (const float*)d_in[0];   // (8,2048,1024) f32
    const float* wts = (const float*)d_in[1];   // (8,2048,8) f32
    const int*   idx = (const int*)d_in[2];     // (8,2048,8) i32
    float* out = (float*)d_out;

    k_rank<<<NCHIP, 128>>>(idx);
    k_scan<<<1, NEXP>>>(out);
    k_init_src<<<(NROWS + 255) / 256, 256>>>();
    k_scatter<<<(NTOT + 255) / 256, 256>>>(idx);
    k_gather<<<NROWS, 256>>>(x, wts, out);
}

// round 7
// speedup vs baseline: 1.0770x; 1.0756x over previous
#include <cuda_runtime.h>

// Problem constants
#define NCHIP   8
#define SEQ     2048
#define TOPK    8
#define HID     1024
#define NEXP    64
#define MAXTOK  2560
#define NPC     (SEQ * TOPK)          // 16384 assignments per chip
#define NTOT    (NCHIP * NPC)         // 131072 assignments total
#define NROWS   (NEXP * MAXTOK)       // 163840 output rows
#define METAL   8

// Output layout (flattened concat, float32):
//   [0, NROWS*HID)                       dispatched
//   [NROWS*HID, NROWS*HID + NROWS*8)     metadata
//   [... , +64)                          tokens_per_expert (value-cast to float)
#define DISP_ELEMS   ((size_t)NROWS * HID)          // 167772160
#define META_OFF     DISP_ELEMS
#define META_ELEMS   ((size_t)NROWS * METAL)        // 1310720
#define TPE_OFF      (META_OFF + META_ELEMS)        // 169082880

// Scratch (static device globals; no allocation allowed)
__device__ int g_counts[NCHIP * NEXP];
__device__ int g_off[NCHIP * NEXP];
__device__ int g_total[NEXP];
__device__ int g_rank[NTOT];
__device__ int g_src[NROWS];

// ---------------------------------------------------------------------------
// Kernel A: per-chip scan-order ranks + per-(chip,expert) counts.
// grid = 8 (one block per chip), block = 128. Each thread owns 128 consecutive
// assignments; ranks within each chunk are assigned sequentially by the owning
// thread, chunk bases come from a per-expert exclusive scan over chunks.
// Fully deterministic (matches jnp stable-argsort rank semantics).
// ---------------------------------------------------------------------------
__global__ void k_rank(const int* __restrict__ idx) {
    __shared__ int cnt[128 * NEXP];   // 32 KB
    const int c = blockIdx.x;
    const int t = threadIdx.x;
    const int* ci = idx + c * NPC;
    int* my = cnt + t * NEXP;

    #pragma unroll
    for (int e = 0; e < NEXP; e++) my[e] = 0;

    const int n0 = t * 128;
    #pragma unroll 4
    for (int i = 0; i < 128; i++) my[ci[n0 + i]]++;
    __syncthreads();

    if (t < NEXP) {
        int run = 0;
        for (int b = 0; b < 128; b++) {
            int v = cnt[b * NEXP + t];
            cnt[b * NEXP + t] = run;
            run += v;
        }
        g_counts[c * NEXP + t] = run;
    }
    __syncthreads();

    #pragma unroll 4
    for (int i = 0; i < 128; i++) {
        int e = ci[n0 + i];
        g_rank[c * NPC + n0 + i] = my[e]++;
    }
}

// ---------------------------------------------------------------------------
// Kernel B: exclusive prefix over chips -> chip offsets; totals ->
// g_total + tokens_per_expert (value-converted to float in the output tail).
// 1 block, 64 threads.
// ---------------------------------------------------------------------------
__global__ void k_scan(float* __restrict__ out) {
    const int e = threadIdx.x;   // 0..63, flat (chip*8 + local) order
    int run = 0;
    for (int c = 0; c < NCHIP; c++) {
        g_off[c * NEXP + e] = run;
        run += g_counts[c * NEXP + e];
    }
    g_total[e] = run;
    out[TPE_OFF + e] = (float)run;
}

// ---------------------------------------------------------------------------
// Kernel C: scatter assignment ids into the row table. dest slots are unique
// by construction, so plain stores. Filled slots per expert are exactly
// [0, g_total[e]) (contiguous packing), so no -1 init pass is needed: the
// gather only reads g_src[r] when slot < g_total[e]. Drop only if dest falls
// off the whole buffer (exact numpy mode="drop" semantics; cannot occur at
// these sizes but kept for safety).
// ---------------------------------------------------------------------------
__global__ void k_scatter(const int* __restrict__ idx) {
    int a = blockIdx.x * blockDim.x + threadIdx.x;
    if (a >= NTOT) return;
    int c = a >> 14;               // a / NPC
    int e = idx[a];
    int dest = e * MAXTOK + g_off[c * NEXP + e] + g_rank[a];
    if (dest < NROWS) g_src[dest] = a;
}

// ---------------------------------------------------------------------------
// Kernel D: the big gather. Grid (slot, expert) = (2560, 64); 256 threads copy
// the 4KB token row (or zero-fill), threads 0/1 write the metadata row.
// ALL output stores use __stcs (evict-first) so the 645MB write stream does
// not evict x (64MB) from L2 — keeps the 8x token re-reads L2-resident and
// DRAM read traffic at the compulsory ~64MB.
// ---------------------------------------------------------------------------
__global__ void __launch_bounds__(256) k_gather(const float* __restrict__ x,
                                                const float* __restrict__ w,
                                                float* __restrict__ out) {
    const int slot = blockIdx.x;
    const int e    = blockIdx.y;
    const int r    = e * MAXTOK + slot;
    const int t    = threadIdx.x;

    float4* drow = reinterpret_cast<float4*>(out + (size_t)r * HID);
    float4* mrow = reinterpret_cast<float4*>(out + META_OFF + (size_t)r * METAL);

    if (slot >= g_total[e]) {
        __stcs(drow + t, make_float4(0.f, 0.f, 0.f, 0.f));
        if (t < 2) __stcs(mrow + t, make_float4(-1.f, -1.f, -1.f, -1.f));
    } else {
        const int a = g_src[r];
        const int c = a >> 14;
        const int n = a & (NPC - 1);
        const int s = n >> 3;
        const int k = n & 7;
        const float4* xr = reinterpret_cast<const float4*>(
            x + ((size_t)c * SEQ + s) * HID);
        __stcs(drow + t, __ldg(&xr[t]));
        if (t == 0) {
            __stcs(mrow, make_float4((float)c, (float)s, (float)k, (float)e));
        } else if (t == 1) {
            float wt = __ldg(&w[(c * SEQ + s) * TOPK + k]);
            __stcs(mrow + 1, make_float4(wt, 0.f, 0.f, 0.f));
        }
    }
}

// ---------------------------------------------------------------------------
extern "C" void kernel_launch(void* const* d_in, const int* in_sizes, int n_in,
                              void* d_out, int out_size) {
    const float* x   = (const float*)d_in[0];   // (8,2048,1024) f32
    const float* wts = (const float*)d_in[1];   // (8,2048,8) f32
    const int*   idx = (const int*)d_in[2];     // (8,2048,8) i32
    float* out = (float*)d_out;

    k_rank<<<NCHIP, 128>>>(idx);
    k_scan<<<1, NEXP>>>(out);
    k_scatter<<<(NTOT + 255) / 256, 256>>>(idx);
    dim3 g(MAXTOK, NEXP);
    k_gather<<<g, 256>>>(x, wts, out);
}

// round 10
// speedup vs baseline: 1.3120x; 1.2182x over previous
#include <cuda_runtime.h>

// Problem constants
#define NCHIP   8
#define SEQ     2048
#define TOPK    8
#define HID     1024
#define NEXP    64
#define MAXTOK  2560
#define NPC     (SEQ * TOPK)          // 16384 assignments per chip
#define NTOT    (NCHIP * NPC)         // 131072 assignments total
#define NROWS   (NEXP * MAXTOK)       // 163840 output rows
#define METAL   8
#define RPB     16                    // rows per gather block (MAXTOK % RPB == 0)

// Output layout (flattened concat, float32):
//   [0, NROWS*HID)                       dispatched
//   [NROWS*HID, NROWS*HID + NROWS*8)     metadata
//   [... , +64)                          tokens_per_expert (value-cast to float)
#define DISP_ELEMS   ((size_t)NROWS * HID)          // 167772160
#define META_OFF     DISP_ELEMS
#define META_ELEMS   ((size_t)NROWS * METAL)        // 1310720
#define TPE_OFF      (META_OFF + META_ELEMS)        // 169082880

// Scratch (static device globals; no allocation allowed)
__device__ int g_counts[NCHIP * NEXP];
__device__ int g_off[NCHIP * NEXP];
__device__ int g_total[NEXP];
__device__ int g_rank[NTOT];
__device__ int g_src[NROWS];

// ---------------------------------------------------------------------------
// Kernel A: per-chip scan-order ranks + per-(chip,expert) counts.
// grid = 8 (one block per chip), block = 128. Deterministic chunked histogram
// + per-expert exclusive scan (matches jnp stable-argsort rank semantics).
// ---------------------------------------------------------------------------
__global__ void k_rank(const int* __restrict__ idx) {
    __shared__ int cnt[128 * NEXP];   // 32 KB
    const int c = blockIdx.x;
    const int t = threadIdx.x;
    const int* ci = idx + c * NPC;
    int* my = cnt + t * NEXP;

    #pragma unroll
    for (int e = 0; e < NEXP; e++) my[e] = 0;

    const int n0 = t * 128;
    #pragma unroll 4
    for (int i = 0; i < 128; i++) my[ci[n0 + i]]++;
    __syncthreads();

    if (t < NEXP) {
        int run = 0;
        for (int b = 0; b < 128; b++) {
            int v = cnt[b * NEXP + t];
            cnt[b * NEXP + t] = run;
            run += v;
        }
        g_counts[c * NEXP + t] = run;
    }
    __syncthreads();

    #pragma unroll 4
    for (int i = 0; i < 128; i++) {
        int e = ci[n0 + i];
        g_rank[c * NPC + n0 + i] = my[e]++;
    }
}

// ---------------------------------------------------------------------------
// Kernel B: exclusive prefix over chips -> chip offsets; totals ->
// g_total + tokens_per_expert (value-converted to float). 1 block, 64 threads.
// ---------------------------------------------------------------------------
__global__ void k_scan(float* __restrict__ out) {
    const int e = threadIdx.x;   // 0..63, flat (chip*8 + local) order
    int run = 0;
    for (int c = 0; c < NCHIP; c++) {
        g_off[c * NEXP + e] = run;
        run += g_counts[c * NEXP + e];
    }
    g_total[e] = run;
    out[TPE_OFF + e] = (float)run;
}

// ---------------------------------------------------------------------------
// Kernel C: scatter assignment ids into the row table. dest slots are unique
// by construction (plain stores). Filled slots per expert are exactly
// [0, g_total[e]) so no -1 init pass is needed.
// ---------------------------------------------------------------------------
__global__ void k_scatter(const int* __restrict__ idx) {
    int a = blockIdx.x * blockDim.x + threadIdx.x;
    if (a >= NTOT) return;
    int c = a >> 14;               // a / NPC
    int e = idx[a];
    int dest = e * MAXTOK + g_off[c * NEXP + e] + g_rank[a];
    if (dest < NROWS) g_src[dest] = a;
}

// ---------------------------------------------------------------------------
// Kernel D: the big gather, MLP-optimized. Grid = (MAXTOK/RPB, NEXP), block
// 256. Prologue: threads 0..RPB-1 resolve g_src for RPB rows into shared and
// write the metadata rows. Main loop: each thread copies one float4 per row,
// fully unrolled over RPB rows -> RPB independent LDG.128s in flight per
// thread (front-batched by ptxas), hiding L2/DRAM latency and saturating BW.
// Output stores use __stcs (evict-first) so the 645MB write stream does not
// evict x (64MB) from L2, keeping the 8x token re-reads L2-resident.
// ---------------------------------------------------------------------------
__global__ void __launch_bounds__(256) k_gather(const float* __restrict__ x,
                                                const float* __restrict__ w,
                                                float* __restrict__ out) {
    __shared__ int s_row[RPB];          // x row index (c*SEQ+s), or -1 = empty

    const int e     = blockIdx.y;
    const int base  = blockIdx.x * RPB;         // slot base within expert
    const int rbase = e * MAXTOK + base;        // global row base
    const int t     = threadIdx.x;

    if (t < RPB) {
        const int slot = base + t;
        const int r    = rbase + t;
        int rowx = -1;
        float4* mrow = reinterpret_cast<float4*>(out + META_OFF + (size_t)r * METAL);
        if (slot < g_total[e]) {
            const int a = g_src[r];
            const int c = a >> 14;
            const int n = a & (NPC - 1);
            const int s = n >> 3;
            const int k = n & 7;
            rowx = c * SEQ + s;
            const float wt = __ldg(&w[rowx * TOPK + k]);
            __stcs(mrow,     make_float4((float)c, (float)s, (float)k, (float)e));
            __stcs(mrow + 1, make_float4(wt, 0.f, 0.f, 0.f));
        } else {
            __stcs(mrow,     make_float4(-1.f, -1.f, -1.f, -1.f));
            __stcs(mrow + 1, make_float4(-1.f, -1.f, -1.f, -1.f));
        }
        s_row[t] = rowx;
    }
    __syncthreads();

    const float4* __restrict__ x4 = reinterpret_cast<const float4*>(x);
    float4* __restrict__ dst = reinterpret_cast<float4*>(out) + (size_t)rbase * (HID / 4);
    const float4 z = make_float4(0.f, 0.f, 0.f, 0.f);

    #pragma unroll
    for (int i = 0; i < RPB; i++) {
        const int rowx = s_row[i];
        float4 v = z;
        if (rowx >= 0) v = __ldg(&x4[(size_t)rowx * (HID / 4) + t]);
        __stcs(&dst[(size_t)i * (HID / 4) + t], v);
    }
}

// ---------------------------------------------------------------------------
extern "C" void kernel_launch(void* const* d_in, const int* in_sizes, int n_in,
                              void* d_out, int out_size) {
    const float* x   = (const float*)d_in[0];   // (8,2048,1024) f32
    const float* wts = (const float*)d_in[1];   // (8,2048,8) f32
    const int*   idx = (const int*)d_in[2];     // (8,2048,8) i32
    float* out = (float*)d_out;

    k_rank<<<NCHIP, 128>>>(idx);
    k_scan<<<1, NEXP>>>(out);
    k_scatter<<<(NTOT + 255) / 256, 256>>>(idx);
    dim3 g(MAXTOK / RPB, NEXP);
    k_gather<<<g, 256>>>(x, wts, out);
}

// round 11
// speedup vs baseline: 1.3156x; 1.0027x over previous
#include <cuda_runtime.h>

// Problem constants
#define NCHIP   8
#define SEQ     2048
#define TOPK    8
#define HID     1024
#define NEXP    64
#define MAXTOK  2560
#define NPC     (SEQ * TOPK)          // 16384 assignments per chip
#define NTOT    (NCHIP * NPC)         // 131072 assignments total
#define NROWS   (NEXP * MAXTOK)       // 163840 output rows
#define METAL   8
#define RPB     16                    // rows per gather block (MAXTOK % RPB == 0)

// Output layout (flattened concat, float32):
//   [0, NROWS*HID)                       dispatched
//   [NROWS*HID, NROWS*HID + NROWS*8)     metadata
//   [... , +64)                          tokens_per_expert (value-cast to float)
#define DISP_ELEMS   ((size_t)NROWS * HID)          // 167772160
#define META_OFF     DISP_ELEMS
#define META_ELEMS   ((size_t)NROWS * METAL)        // 1310720
#define TPE_OFF      (META_OFF + META_ELEMS)        // 169082880

// Scratch (static device globals; no allocation allowed)
__device__ int g_counts[NCHIP * NEXP];
__device__ int g_off[NCHIP * NEXP];
__device__ int g_total[NEXP];
__device__ int g_rank[NTOT];
__device__ int g_src[NROWS];

// ---------------------------------------------------------------------------
// Kernel A: per-chip scan-order ranks + per-(chip,expert) counts.
// grid = 8 (one block per chip), block = 128. Deterministic chunked histogram
// + per-expert exclusive scan (matches jnp stable-argsort rank semantics).
// ---------------------------------------------------------------------------
__global__ void k_rank(const int* __restrict__ idx) {
    __shared__ int cnt[128 * NEXP];   // 32 KB
    const int c = blockIdx.x;
    const int t = threadIdx.x;
    const int* ci = idx + c * NPC;
    int* my = cnt + t * NEXP;

    #pragma unroll
    for (int e = 0; e < NEXP; e++) my[e] = 0;

    const int n0 = t * 128;
    #pragma unroll 4
    for (int i = 0; i < 128; i++) my[ci[n0 + i]]++;
    __syncthreads();

    if (t < NEXP) {
        int run = 0;
        for (int b = 0; b < 128; b++) {
            int v = cnt[b * NEXP + t];
            cnt[b * NEXP + t] = run;
            run += v;
        }
        g_counts[c * NEXP + t] = run;
    }
    __syncthreads();

    #pragma unroll 4
    for (int i = 0; i < 128; i++) {
        int e = ci[n0 + i];
        g_rank[c * NPC + n0 + i] = my[e]++;
    }
}

// ---------------------------------------------------------------------------
// Kernel B: exclusive prefix over chips -> chip offsets; totals ->
// g_total + tokens_per_expert (value-converted to float). 1 block, 64 threads.
// ---------------------------------------------------------------------------
__global__ void k_scan(float* __restrict__ out) {
    const int e = threadIdx.x;   // 0..63, flat (chip*8 + local) order
    int run = 0;
    for (int c = 0; c < NCHIP; c++) {
        g_off[c * NEXP + e] = run;
        run += g_counts[c * NEXP + e];
    }
    g_total[e] = run;
    out[TPE_OFF + e] = (float)run;
}

// ---------------------------------------------------------------------------
// Kernel C: scatter assignment ids into the row table. dest slots are unique
// by construction (plain stores). Filled slots per expert are exactly
// [0, g_total[e]) so no -1 init pass is needed.
// ---------------------------------------------------------------------------
__global__ void k_scatter(const int* __restrict__ idx) {
    int a = blockIdx.x * blockDim.x + threadIdx.x;
    if (a >= NTOT) return;
    int c = a >> 14;               // a / NPC
    int e = idx[a];
    int dest = e * MAXTOK + g_off[c * NEXP + e] + g_rank[a];
    if (dest < NROWS) g_src[dest] = a;
}

// ---------------------------------------------------------------------------
// Kernel D: the big gather, MLP-optimized. Grid = (MAXTOK/RPB, NEXP), block
// 256. Prologue: threads 0..RPB-1 resolve g_src for RPB rows into shared and
// write the metadata rows. Main loop: each thread copies one float4 per row,
// fully unrolled over RPB rows -> RPB independent LDG.128s in flight per
// thread (front-batched by ptxas), hiding L2/DRAM latency and saturating BW.
// Output stores use __stcs (evict-first) so the 645MB write stream does not
// evict x (64MB) from L2, keeping the 8x token re-reads L2-resident.
// ---------------------------------------------------------------------------
__global__ void __launch_bounds__(256) k_gather(const float* __restrict__ x,
                                                const float* __restrict__ w,
                                                float* __restrict__ out) {
    __shared__ int s_row[RPB];          // x row index (c*SEQ+s), or -1 = empty

    const int e     = blockIdx.y;
    const int base  = blockIdx.x * RPB;         // slot base within expert
    const int rbase = e * MAXTOK + base;        // global row base
    const int t     = threadIdx.x;

    if (t < RPB) {
        const int slot = base + t;
        const int r    = rbase + t;
        int rowx = -1;
        float4* mrow = reinterpret_cast<float4*>(out + META_OFF + (size_t)r * METAL);
        if (slot < g_total[e]) {
            const int a = g_src[r];
            const int c = a >> 14;
            const int n = a & (NPC - 1);
            const int s = n >> 3;
            const int k = n & 7;
            rowx = c * SEQ + s;
            const float wt = __ldg(&w[rowx * TOPK + k]);
            __stcs(mrow,     make_float4((float)c, (float)s, (float)k, (float)e));
            __stcs(mrow + 1, make_float4(wt, 0.f, 0.f, 0.f));
        } else {
            __stcs(mrow,     make_float4(-1.f, -1.f, -1.f, -1.f));
            __stcs(mrow + 1, make_float4(-1.f, -1.f, -1.f, -1.f));
        }
        s_row[t] = rowx;
    }
    __syncthreads();

    const float4* __restrict__ x4 = reinterpret_cast<const float4*>(x);
    float4* __restrict__ dst = reinterpret_cast<float4*>(out) + (size_t)rbase * (HID / 4);
    const float4 z = make_float4(0.f, 0.f, 0.f, 0.f);

    #pragma unroll
    for (int i = 0; i < RPB; i++) {
        const int rowx = s_row[i];
        float4 v = z;
        if (rowx >= 0) v = __ldg(&x4[(size_t)rowx * (HID / 4) + t]);
        __stcs(&dst[(size_t)i * (HID / 4) + t], v);
    }
}

// ---------------------------------------------------------------------------
extern "C" void kernel_launch(void* const* d_in, const int* in_sizes, int n_in,
                              void* d_out, int out_size) {
    const float* x   = (const float*)d_in[0];   // (8,2048,1024) f32
    const float* wts = (const float*)d_in[1];   // (8,2048,8) f32
    const int*   idx = (const int*)d_in[2];     // (8,2048,8) i32
    float* out = (float*)d_out;

    k_rank<<<NCHIP, 128>>>(idx);
    k_scan<<<1, NEXP>>>(out);
    k_scatter<<<(NTOT + 255) / 256, 256>>>(idx);
    dim3 g(MAXTOK / RPB, NEXP);
    k_gather<<<g, 256>>>(x, wts, out);
}

// round 12
// speedup vs baseline: 1.3170x; 1.0010x over previous
#include <cuda_runtime.h>

// Problem constants
#define NCHIP   8
#define SEQ     2048
#define TOPK    8
#define HID     1024
#define NEXP    64
#define MAXTOK  2560
#define NPC     (SEQ * TOPK)          // 16384 assignments per chip
#define NTOT    (NCHIP * NPC)         // 131072 assignments total
#define NROWS   (NEXP * MAXTOK)       // 163840 output rows
#define METAL   8
#define RPB     16                    // rows per gather block (MAXTOK % RPB == 0)

// Output layout (flattened concat, float32):
//   [0, NROWS*HID)                       dispatched
//   [NROWS*HID, NROWS*HID + NROWS*8)     metadata
//   [... , +64)                          tokens_per_expert (value-cast to float)
#define DISP_ELEMS   ((size_t)NROWS * HID)          // 167772160
#define META_OFF     DISP_ELEMS
#define META_ELEMS   ((size_t)NROWS * METAL)        // 1310720
#define TPE_OFF      (META_OFF + META_ELEMS)        // 169082880

// Scratch (static device globals; no allocation allowed)
__device__ int g_counts[NCHIP * NEXP];
__device__ int g_off[NCHIP * NEXP];
__device__ int g_total[NEXP];
__device__ int g_rank[NTOT];
__device__ int g_src[NROWS];

// ---------------------------------------------------------------------------
// Kernel A: per-chip scan-order ranks + per-(chip,expert) counts.
// grid = 8 (one block per chip), block = 128. Deterministic chunked histogram
// + per-expert exclusive scan (matches jnp stable-argsort rank semantics).
// ---------------------------------------------------------------------------
__global__ void k_rank(const int* __restrict__ idx) {
    __shared__ int cnt[128 * NEXP];   // 32 KB
    const int c = blockIdx.x;
    const int t = threadIdx.x;
    const int* ci = idx + c * NPC;
    int* my = cnt + t * NEXP;

    #pragma unroll
    for (int e = 0; e < NEXP; e++) my[e] = 0;

    const int n0 = t * 128;
    #pragma unroll 4
    for (int i = 0; i < 128; i++) my[ci[n0 + i]]++;
    __syncthreads();

    if (t < NEXP) {
        int run = 0;
        for (int b = 0; b < 128; b++) {
            int v = cnt[b * NEXP + t];
            cnt[b * NEXP + t] = run;
            run += v;
        }
        g_counts[c * NEXP + t] = run;
    }
    __syncthreads();

    #pragma unroll 4
    for (int i = 0; i < 128; i++) {
        int e = ci[n0 + i];
        g_rank[c * NPC + n0 + i] = my[e]++;
    }
}

// ---------------------------------------------------------------------------
// Kernel B: exclusive prefix over chips -> chip offsets; totals ->
// g_total + tokens_per_expert (value-converted to float). 1 block, 64 threads.
// ---------------------------------------------------------------------------
__global__ void k_scan(float* __restrict__ out) {
    const int e = threadIdx.x;   // 0..63, flat (chip*8 + local) order
    int run = 0;
    for (int c = 0; c < NCHIP; c++) {
        g_off[c * NEXP + e] = run;
        run += g_counts[c * NEXP + e];
    }
    g_total[e] = run;
    out[TPE_OFF + e] = (float)run;
}

// ---------------------------------------------------------------------------
// Kernel C: scatter assignment ids into the row table. dest slots are unique
// by construction (plain stores). Filled slots per expert are exactly
// [0, g_total[e]) so no -1 init pass is needed.
// ---------------------------------------------------------------------------
__global__ void k_scatter(const int* __restrict__ idx) {
    int a = blockIdx.x * blockDim.x + threadIdx.x;
    if (a >= NTOT) return;
    int c = a >> 14;               // a / NPC
    int e = idx[a];
    int dest = e * MAXTOK + g_off[c * NEXP + e] + g_rank[a];
    if (dest < NROWS) g_src[dest] = a;
}

// ---------------------------------------------------------------------------
// Kernel D: the big gather, MLP-optimized. Grid = (MAXTOK/RPB, NEXP), block
// 256. Prologue: threads 0..RPB-1 resolve g_src for RPB rows into shared and
// write the metadata rows. Main loop: each thread copies one float4 per row,
// fully unrolled over RPB rows -> RPB independent LDG.128s in flight per
// thread (front-batched by ptxas), hiding L2/DRAM latency and saturating BW.
// Output stores use __stcs (evict-first) so the 645MB write stream does not
// evict x (64MB) from L2, keeping the 8x token re-reads L2-resident.
// ---------------------------------------------------------------------------
__global__ void __launch_bounds__(256) k_gather(const float* __restrict__ x,
                                                const float* __restrict__ w,
                                                float* __restrict__ out) {
    __shared__ int s_row[RPB];          // x row index (c*SEQ+s), or -1 = empty

    const int e     = blockIdx.y;
    const int base  = blockIdx.x * RPB;         // slot base within expert
    const int rbase = e * MAXTOK + base;        // global row base
    const int t     = threadIdx.x;

    if (t < RPB) {
        const int slot = base + t;
        const int r    = rbase + t;
        int rowx = -1;
        float4* mrow = reinterpret_cast<float4*>(out + META_OFF + (size_t)r * METAL);
        if (slot < g_total[e]) {
            const int a = g_src[r];
            const int c = a >> 14;
            const int n = a & (NPC - 1);
            const int s = n >> 3;
            const int k = n & 7;
            rowx = c * SEQ + s;
            const float wt = __ldg(&w[rowx * TOPK + k]);
            __stcs(mrow,     make_float4((float)c, (float)s, (float)k, (float)e));
            __stcs(mrow + 1, make_float4(wt, 0.f, 0.f, 0.f));
        } else {
            __stcs(mrow,     make_float4(-1.f, -1.f, -1.f, -1.f));
            __stcs(mrow + 1, make_float4(-1.f, -1.f, -1.f, -1.f));
        }
        s_row[t] = rowx;
    }
    __syncthreads();

    const float4* __restrict__ x4 = reinterpret_cast<const float4*>(x);
    float4* __restrict__ dst = reinterpret_cast<float4*>(out) + (size_t)rbase * (HID / 4);
    const float4 z = make_float4(0.f, 0.f, 0.f, 0.f);

    #pragma unroll
    for (int i = 0; i < RPB; i++) {
        const int rowx = s_row[i];
        float4 v = z;
        if (rowx >= 0) v = __ldg(&x4[(size_t)rowx * (HID / 4) + t]);
        __stcs(&dst[(size_t)i * (HID / 4) + t], v);
    }
}

// ---------------------------------------------------------------------------
extern "C" void kernel_launch(void* const* d_in, const int* in_sizes, int n_in,
                              void* d_out, int out_size) {
    const float* x   = (const float*)d_in[0];   // (8,2048,1024) f32
    const float* wts = (const float*)d_in[1];   // (8,2048,8) f32
    const int*   idx = (const int*)d_in[2];     // (8,2048,8) i32
    float* out = (float*)d_out;

    k_rank<<<NCHIP, 128>>>(idx);
    k_scan<<<1, NEXP>>>(out);
    k_scatter<<<(NTOT + 255) / 256, 256>>>(idx);
    dim3 g(MAXTOK / RPB, NEXP);
    k_gather<<<g, 256>>>(x, wts, out);
}